// round 14
// baseline (speedup 1.0000x reference)
#include <cuda_runtime.h>
#include <cuda_bf16.h>
#include <math.h>
#include <stdint.h>

// ---------------------------------------------------------------------------
// Problem constants
// ---------------------------------------------------------------------------
#define NB   4        // batch
#define NT   1024     // time steps
#define NL   512      // latent / emb
#define NV   50257    // vocab
#define NR   (NB*NT)  // 4096 rows
#define NVP  50304    // padded vocab pitch (= 393*128, 16B-aligned rows)
#define NCT  393      // column tiles in unembed

// big GEMM tiling (cp.async pipelined)
#define UBM 128
#define UBN 128
#define UBK 16
#define UST 4
#define UAS (UBM*20)
#define UBS (UBK*132)
#define FUSED_SMEM (UST*(UAS+UBS)*4)   // 74752 bytes (covers all roles)

#define SCAN_CTAS 64
#define GRID_CTAS 296                  // 2 waves x 148 SMs
#define NQ_XW     128                  // XW0 tiles (8 chunks x 4 b x 4 ct)
#define NQ_UN     (32*NCT)             // 12576 unembed tiles (32 t-groups)
#define NQ_TOT    (NQ_XW + NQ_UN)

#define NGRP 8                         // barrier groups (8 CTAs each)
#define GSTRIDE 64                     // uints = 256B between group counters

// ---------------------------------------------------------------------------
// Scratch (device globals — no allocation allowed)
// ---------------------------------------------------------------------------
__device__ float g_bufA[NR * NL];     // XW0 (= embed[x]@Wx0 + b0), [b][t] rows
__device__ float g_bufB[NR * NL];     // H1, T-MAJOR rows [t][b], tf32-rounded
__device__ float g_wu[NL * NVP];      // Wu, tf32-rounded + padded (on demand)
__device__ float4 g_h0[2][NL];        // depth-2 ring, layer-0 h, [k]={b0..b3}
__device__ float4 g_h1[2][NL];        // depth-2 ring, layer-1 h
__device__ unsigned g_gbar[NGRP * GSTRIDE];  // hierarchical barrier counters
__device__ unsigned g_q;              // work-stealing queue head
__device__ unsigned g_xwcnt[32];      // per-(batch,128-t-chunk) XW0 tile count
__device__ unsigned g_wuflag[NCT];    // per-column-band Wu conversion flag
__device__ unsigned g_smids[SCAN_CTAS];  // scan CTA -> smid+1
__device__ unsigned g_smidcnt;        // #scan CTAs that published smid

// ---------------------------------------------------------------------------
// Helpers
// ---------------------------------------------------------------------------
__device__ __forceinline__ unsigned f2tf32(float f) {
    unsigned u;
    asm("cvt.rna.tf32.f32 %0, %1;" : "=r"(u) : "f"(f));
    return u;
}

__device__ __forceinline__ void mma_tf32(float c[4], const unsigned a[4],
                                         const unsigned b[2]) {
    asm volatile(
        "mma.sync.aligned.m16n8k8.row.col.f32.tf32.tf32.f32 "
        "{%0,%1,%2,%3},{%4,%5,%6,%7},{%8,%9},{%0,%1,%2,%3};"
        : "+f"(c[0]), "+f"(c[1]), "+f"(c[2]), "+f"(c[3])
        : "r"(a[0]), "r"(a[1]), "r"(a[2]), "r"(a[3]), "r"(b[0]), "r"(b[1]));
}

__device__ __forceinline__ void cp16(uint32_t dst, const void* src) {
    asm volatile("cp.async.cg.shared.global [%0], [%1], 16;\n"
                 :: "r"(dst), "l"(src));
}

__device__ __forceinline__ unsigned ld_acq(const unsigned* p) {
    unsigned v;
    asm volatile("ld.acquire.gpu.global.u32 %0, [%1];"
                 : "=r"(v) : "l"(p) : "memory");
    return v;
}

__device__ __forceinline__ void st_rel(unsigned* p, unsigned v) {
    asm volatile("st.release.gpu.global.u32 [%0], %1;"
                 :: "l"(p), "r"(v) : "memory");
}

__device__ __forceinline__ void red_rel(unsigned* p) {
    asm volatile("red.release.gpu.global.add.u32 [%0], %1;"
                 :: "l"(p), "r"(1u) : "memory");
}

// min over the 8 group counters, all loads issued back-to-back (MLP=8)
__device__ __forceinline__ unsigned bar_min() {
    unsigned v[NGRP];
#pragma unroll
    for (int g = 0; g < NGRP; ++g) v[g] = ld_acq(&g_gbar[g * GSTRIDE]);
    unsigned m = v[0];
#pragma unroll
    for (int g = 1; g < NGRP; ++g) m = min(m, v[g]);
    return m;
}

// ---------------------------------------------------------------------------
// init: reset all counters + zero both h rings
// ---------------------------------------------------------------------------
__global__ void init_kernel() {
    const int tid = threadIdx.x;
    if (tid == 0) { g_q = 0u; g_smidcnt = 0u; }
    for (int i = tid; i < NGRP * GSTRIDE; i += 256) g_gbar[i] = 0u;
    for (int i = tid; i < SCAN_CTAS; i += 256) g_smids[i] = 0u;
    for (int i = tid; i < 32; i += 256) g_xwcnt[i] = 0u;
    for (int i = tid; i < NCT; i += 256) g_wuflag[i] = 0u;
    float4 z = make_float4(0.f, 0.f, 0.f, 0.f);
    for (int i = tid; i < 2 * NL; i += 256) {
        ((float4*)g_h0)[i] = z;
        ((float4*)g_h1)[i] = z;
    }
}

// ---------------------------------------------------------------------------
// FUSED kernel.
//   bids [0,64):  scan. Hierarchical 8x8 barrier: arrive -> own group
//                 counter (8-deep drain, parallel across LTS slices); wait ->
//                 single poller reads all 8 counters (MLP=8) and checks min.
//                 XW0 prefetched BEFORE the wait except at chunk starts.
//   bids [64,296): workers (R13: self-evict off scan SMs, then steal tiles).
// ---------------------------------------------------------------------------
__global__ __launch_bounds__(256, 2)
void fused_all(const int* __restrict__ x,
               const float* __restrict__ embed,
               const float* __restrict__ Wx0,
               const float* __restrict__ b0,
               const float* __restrict__ Wh0,
               const float* __restrict__ Wx1,
               const float* __restrict__ Wh1,
               const float* __restrict__ b1,
               const float* __restrict__ Wu,
               const float* __restrict__ bias,
               float* __restrict__ XW0,
               float* __restrict__ H1,
               float* __restrict__ C) {
    extern __shared__ float sm[];
    const int tid = threadIdx.x;

    if (blockIdx.x < SCAN_CTAS) {
        // ===================== SCAN =====================
        if (tid == 0) {
            unsigned smid;
            asm("mov.u32 %0, %%smid;" : "=r"(smid));
            st_rel(&g_smids[blockIdx.x], smid + 1u);
            red_rel(&g_smidcnt);
        }

        float4* hT0 = (float4*)sm;            // 512
        float4* hT1 = hT0 + 512;              // 512
        float4* sred0 = hT1 + 512;            // [8][4]
        float4* sred1 = sred0 + 32;           // [8][4]

        const int lane = tid & 31;
        const int warp = tid >> 5;
        const int blk  = blockIdx.x;
        const int jw   = blk * 8 + warp;
        unsigned* const mygrp = &g_gbar[(blk >> 3) * GSTRIDE];

        float w0[16], w1x[16], w1h[16];
#pragma unroll
        for (int i = 0; i < 16; ++i) {
            const size_t k = (size_t)(lane + 32 * i) * NL + jw;
            w0[i]  = Wh0[k];
            w1x[i] = Wx1[k];
            w1h[i] = Wh1[k];
        }
        const float bias1 = (lane >= 4 && lane < 8) ? b1[jw] : 0.f;
        const int i0 = tid, i1 = tid + 256;

        for (int e = 0; e <= NT; ++e) {
            const bool do0 = (e < NT);
            const bool do1 = (e >= 1);
            const bool chunk_start = do0 && ((e & 127) == 0);

            // prefetch XW0 BEFORE the wait — safe for non-chunk-start epochs:
            // the chunk gate at epoch (e & ~127) + its syncthreads already
            // established happens-before with the producers of this chunk.
            float xw = 0.f;
            if (do0 && !chunk_start && lane < 4)
                xw = __ldcg(&XW0[((size_t)lane * NT + e) * NL + jw]);

            if (tid == 0) {
                if (chunk_start) {
                    const int c = e >> 7;
                    for (int b = 0; b < 4; ++b)
                        while (ld_acq(&g_xwcnt[b * 8 + c]) < 4u) { }
                }
                if (e > 0) {
                    const unsigned tgt = 8u * (unsigned)e;
                    while (bar_min() < tgt) { }
                }
            }
            __syncthreads();

            if (chunk_start && lane < 4)
                xw = __ldcg(&XW0[((size_t)lane * NT + e) * NL + jw]);

            hT0[i0] = __ldcg(&g_h0[(e + 1) & 1][i0]);
            hT0[i1] = __ldcg(&g_h0[(e + 1) & 1][i1]);
            if (do1) {
                hT1[i0] = __ldcg(&g_h1[e & 1][i0]);
                hT1[i1] = __ldcg(&g_h1[e & 1][i1]);
            }
            __syncthreads();

            float ax = 0.f, ay = 0.f, az = 0.f, aw = 0.f;
            float bx = 0.f, by = 0.f, bz = 0.f, bw = 0.f;
#pragma unroll
            for (int i = 0; i < 16; ++i) {
                const float4 hv = hT0[lane + 32 * i];
                const float wa = w0[i];
                const float wb = w1x[i];
                ax = fmaf(wa, hv.x, ax);
                ay = fmaf(wa, hv.y, ay);
                az = fmaf(wa, hv.z, az);
                aw = fmaf(wa, hv.w, aw);
                bx = fmaf(wb, hv.x, bx);
                by = fmaf(wb, hv.y, by);
                bz = fmaf(wb, hv.z, bz);
                bw = fmaf(wb, hv.w, bw);
            }
            if (do1) {
#pragma unroll
                for (int i = 0; i < 16; ++i) {
                    const float4 hv = hT1[lane + 32 * i];
                    const float wb = w1h[i];
                    bx = fmaf(wb, hv.x, bx);
                    by = fmaf(wb, hv.y, by);
                    bz = fmaf(wb, hv.z, bz);
                    bw = fmaf(wb, hv.w, bw);
                }
            }

#pragma unroll
            for (int off = 16; off >= 4; off >>= 1) {
                ax += __shfl_down_sync(0xffffffffu, ax, off);
                ay += __shfl_down_sync(0xffffffffu, ay, off);
                az += __shfl_down_sync(0xffffffffu, az, off);
                aw += __shfl_down_sync(0xffffffffu, aw, off);
                bx += __shfl_down_sync(0xffffffffu, bx, off);
                by += __shfl_down_sync(0xffffffffu, by, off);
                bz += __shfl_down_sync(0xffffffffu, bz, off);
                bw += __shfl_down_sync(0xffffffffu, bw, off);
            }
            if (lane < 4) {
                sred0[warp * 4 + lane] = make_float4(ax, ay, az, aw);
                sred1[warp * 4 + lane] = make_float4(bx, by, bz, bw);
            }
            __syncwarp();

            if (do0 && lane < 4) {
                const float* p = (const float*)&sred0[warp * 4];
                const float s = p[lane] + p[4 + lane] + p[8 + lane] + p[12 + lane];
                const float hn = tanhf(s + xw);
                __stcg(&((float*)&g_h0[e & 1][jw])[lane], hn);
            }
            if (do1 && lane >= 4 && lane < 8) {
                const int b = lane - 4;
                const float* p = (const float*)&sred1[warp * 4];
                const float s = p[b] + p[4 + b] + p[8 + b] + p[12 + b];
                const float hn = tanhf(s + bias1);
                __stcg(&((float*)&g_h1[(e + 1) & 1][jw])[b], hn);
                // T-MAJOR: row = t*4 + b  (t = e-1)
                H1[((size_t)(e - 1) * 4 + b) * NL + jw] =
                    __uint_as_float(f2tf32(hn));
            }

            __syncthreads();   // CTA-wide HB edge: writes -> tid0's release
            if (tid == 0) red_rel(mygrp);
        }
        return;
    }

    // ===================== WORKER =====================
    __shared__ unsigned s_exit, s_tile;

    if (tid == 0) {
        unsigned mysm;
        asm("mov.u32 %0, %%smid;" : "=r"(mysm));
        while (ld_acq(&g_smidcnt) < (unsigned)SCAN_CTAS) { }
        unsigned ex = 0u;
        for (int i = 0; i < SCAN_CTAS; ++i)
            if (ld_acq(&g_smids[i]) == mysm + 1u) { ex = 1u; break; }
        s_exit = ex;
    }
    __syncthreads();
    if (s_exit) return;   // leave the scan CTA alone on this SM

    const int lane = tid & 31;
    const int warp = tid >> 5;
    const int wm = warp & 1;
    const int wn = warp >> 1;
    const int g  = lane >> 2;
    const int t4 = lane & 3;

    for (;;) {
        __syncthreads();
        if (tid == 0) s_tile = atomicAdd(&g_q, 1u);
        __syncthreads();
        const unsigned tile = s_tile;
        if (tile >= (unsigned)NQ_TOT) return;

        if (tile < (unsigned)NQ_XW) {
            // ---------- XW0 GEMM tile (chunk-ordered) ----------
            const int uid2 = (int)tile;
            const int c  = uid2 >> 4;
            const int b  = (uid2 >> 2) & 3;
            const int ct = uid2 & 3;
            const int rowBase = b * 1024 + c * 128;
            const int nb = ct * 128;
            const int rt = b * 8 + c;

            float* As = sm;                 // [2][128][20]
            float* Bs = sm + 2 * 128 * 20;  // [2][16][132]

            float acc[4][4][4];
#pragma unroll
            for (int a = 0; a < 4; ++a)
#pragma unroll
                for (int b2 = 0; b2 < 4; ++b2)
#pragma unroll
                    for (int e2 = 0; e2 < 4; ++e2) acc[a][b2][e2] = 0.f;

            const int ar0 = tid >> 2, af0 = tid & 3;
            const int ar1 = (tid + 256) >> 2;
            const float* arow0 = embed + (size_t)x[rowBase + ar0] * NL;
            const float* arow1 = embed + (size_t)x[rowBase + ar1] * NL;
            const int bk0 = tid >> 5, bc = tid & 31;
            const int bk1 = bk0 + 8;

            float4 pa0 = *(const float4*)(arow0 + af0 * 4);
            float4 pa1 = *(const float4*)(arow1 + af0 * 4);
            float4 pb0 = *(const float4*)(Wx0 + (size_t)bk0 * NL + nb + bc * 4);
            float4 pb1 = *(const float4*)(Wx0 + (size_t)bk1 * NL + nb + bc * 4);

            int w = 0;
            for (int kb = 0; kb < NL; kb += UBK) {
                {
                    float4 v;
                    v.x = __uint_as_float(f2tf32(pa0.x));
                    v.y = __uint_as_float(f2tf32(pa0.y));
                    v.z = __uint_as_float(f2tf32(pa0.z));
                    v.w = __uint_as_float(f2tf32(pa0.w));
                    *(float4*)&As[w * (128 * 20) + ar0 * 20 + af0 * 4] = v;
                    v.x = __uint_as_float(f2tf32(pa1.x));
                    v.y = __uint_as_float(f2tf32(pa1.y));
                    v.z = __uint_as_float(f2tf32(pa1.z));
                    v.w = __uint_as_float(f2tf32(pa1.w));
                    *(float4*)&As[w * (128 * 20) + ar1 * 20 + af0 * 4] = v;
                    v.x = __uint_as_float(f2tf32(pb0.x));
                    v.y = __uint_as_float(f2tf32(pb0.y));
                    v.z = __uint_as_float(f2tf32(pb0.z));
                    v.w = __uint_as_float(f2tf32(pb0.w));
                    *(float4*)&Bs[w * (16 * 132) + bk0 * 132 + bc * 4] = v;
                    v.x = __uint_as_float(f2tf32(pb1.x));
                    v.y = __uint_as_float(f2tf32(pb1.y));
                    v.z = __uint_as_float(f2tf32(pb1.z));
                    v.w = __uint_as_float(f2tf32(pb1.w));
                    *(float4*)&Bs[w * (16 * 132) + bk1 * 132 + bc * 4] = v;
                }
                __syncthreads();

                if (kb + UBK < NL) {
                    pa0 = *(const float4*)(arow0 + kb + UBK + af0 * 4);
                    pa1 = *(const float4*)(arow1 + kb + UBK + af0 * 4);
                    pb0 = *(const float4*)(Wx0 + (size_t)(kb + UBK + bk0) * NL + nb + bc * 4);
                    pb1 = *(const float4*)(Wx0 + (size_t)(kb + UBK + bk1) * NL + nb + bc * 4);
                }

                const float* Aw = &As[w * (128 * 20)];
                const float* Bw = &Bs[w * (16 * 132)];
#pragma unroll
                for (int ks = 0; ks < UBK; ks += 8) {
                    unsigned af[4][4], bf[4][2];
#pragma unroll
                    for (int im = 0; im < 4; ++im) {
                        const int m0 = wm * 64 + im * 16;
                        const float* a0 = Aw + (m0 + g) * 20 + ks + t4;
                        const float* a1 = Aw + (m0 + g + 8) * 20 + ks + t4;
                        af[im][0] = __float_as_uint(a0[0]);
                        af[im][1] = __float_as_uint(a1[0]);
                        af[im][2] = __float_as_uint(a0[4]);
                        af[im][3] = __float_as_uint(a1[4]);
                    }
#pragma unroll
                    for (int in = 0; in < 4; ++in) {
                        const int n0 = wn * 32 + in * 8;
                        bf[in][0] = __float_as_uint(Bw[(ks + t4) * 132 + n0 + g]);
                        bf[in][1] = __float_as_uint(Bw[(ks + t4 + 4) * 132 + n0 + g]);
                    }
#pragma unroll
                    for (int im = 0; im < 4; ++im)
#pragma unroll
                        for (int in = 0; in < 4; ++in)
                            mma_tf32(acc[im][in], af[im], bf[in]);
                }
                w ^= 1;
                __syncthreads();
            }

#pragma unroll
            for (int im = 0; im < 4; ++im) {
                const int r0 = rowBase + wm * 64 + im * 16 + g;
#pragma unroll
                for (int in = 0; in < 4; ++in) {
                    const int c0 = nb + wn * 32 + in * 8 + t4 * 2;
#pragma unroll
                    for (int e2 = 0; e2 < 4; ++e2) {
                        const int row = r0 + ((e2 & 2) ? 8 : 0);
                        const int col = c0 + (e2 & 1);
                        XW0[(size_t)row * NL + col] = acc[im][in][e2] + b0[col];
                    }
                }
            }
            __syncthreads();
            if (tid == 0) red_rel(&g_xwcnt[rt]);
        } else {
            // ---------- UNEMBED tile (32-step t-group granularity) ----------
            const int u  = (int)(tile - NQ_XW);
            const int jj = u / NCT;               // t-group 0..31
            const int xq = u % NCT;               // column tile 0..392
            const int rowBase = jj * 128;         // T-MAJOR rows
            const int nb      = xq * UBN;

            if (jj == 0) {
                // CONVERT band xq: g_wu[k][nb..nb+128) = tf32(Wu)
                for (int idx = tid; idx < NL * UBN; idx += 256) {
                    const int k = idx >> 7;
                    const int n = nb + (idx & 127);
                    g_wu[(size_t)k * NVP + n] =
                        (n < NV) ? __uint_as_float(f2tf32(Wu[(size_t)k * NV + n]))
                                 : 0.f;
                }
                __syncthreads();
                if (tid == 0) red_rel(&g_wuflag[xq]);
            } else {
                if (tid == 0)
                    while (ld_acq(&g_wuflag[xq]) < 1u) __nanosleep(128);
            }

            // H1 rows cover t in [32jj, 32jj+32): counters >= 8*(32*(jj+1)+1)
            const unsigned tgt = 8u * (unsigned)(32 * (jj + 1) + 1);
            if (tid == 0)
                while (bar_min() < tgt) __nanosleep(256);
            __syncthreads();

            const float* A = H1;
            const uint32_t smem_u32 = (uint32_t)__cvta_generic_to_shared(sm);

            float acc[4][4][4];
#pragma unroll
            for (int a = 0; a < 4; ++a)
#pragma unroll
                for (int b2 = 0; b2 < 4; ++b2)
#pragma unroll
                    for (int e2 = 0; e2 < 4; ++e2) acc[a][b2][e2] = 0.f;

            const int arow = tid >> 2;
            const int ac4  = tid & 3;
            const float* aptr0 = A + (size_t)(rowBase + arow) * NL + ac4 * 4;
            const float* aptr1 = A + (size_t)(rowBase + arow + 64) * NL + ac4 * 4;
            const int bkr0 = tid >> 5;
            const int bc0  = tid & 31;
            const float* bptr0 = g_wu + (size_t)bkr0 * NVP + nb + bc0 * 4;
            const float* bptr1 = g_wu + (size_t)(bkr0 + 8) * NVP + nb + bc0 * 4;

            const uint32_t adst0 = smem_u32 + (arow * 20 + ac4 * 4) * 4;
            const uint32_t adst1 = smem_u32 + ((arow + 64) * 20 + ac4 * 4) * 4;
            const uint32_t bdst0 = smem_u32 + (UST * UAS + bkr0 * 132 + bc0 * 4) * 4;
            const uint32_t bdst1 = smem_u32 + (UST * UAS + (bkr0 + 8) * 132 + bc0 * 4) * 4;

            const int NKT = NL / UBK;

#pragma unroll
            for (int s = 0; s < UST - 1; ++s) {
                const int kb = s * UBK;
                cp16(adst0 + s * UAS * 4, aptr0 + kb);
                cp16(adst1 + s * UAS * 4, aptr1 + kb);
                cp16(bdst0 + s * UBS * 4, bptr0 + (size_t)kb * NVP);
                cp16(bdst1 + s * UBS * 4, bptr1 + (size_t)kb * NVP);
                asm volatile("cp.async.commit_group;\n" ::);
            }

            for (int kt = 0; kt < NKT; ++kt) {
                asm volatile("cp.async.wait_group 2;\n" ::);
                __syncthreads();

                if (kt + UST - 1 < NKT) {
                    const int s  = (kt + UST - 1) & (UST - 1);
                    const int kb = (kt + UST - 1) * UBK;
                    cp16(adst0 + s * UAS * 4, aptr0 + kb);
                    cp16(adst1 + s * UAS * 4, aptr1 + kb);
                    cp16(bdst0 + s * UBS * 4, bptr0 + (size_t)kb * NVP);
                    cp16(bdst1 + s * UBS * 4, bptr1 + (size_t)kb * NVP);
                }
                asm volatile("cp.async.commit_group;\n" ::);

                const float* Aw = sm + (kt & (UST - 1)) * UAS;
                const float* Bw = sm + UST * UAS + (kt & (UST - 1)) * UBS;
#pragma unroll
                for (int ks = 0; ks < UBK; ks += 8) {
                    unsigned af[4][4], bf[4][2];
#pragma unroll
                    for (int im = 0; im < 4; ++im) {
                        const int m0 = wm * 64 + im * 16;
                        const float* a0 = Aw + (m0 + g) * 20 + ks + t4;
                        const float* a1 = Aw + (m0 + g + 8) * 20 + ks + t4;
                        af[im][0] = __float_as_uint(a0[0]);
                        af[im][1] = __float_as_uint(a1[0]);
                        af[im][2] = __float_as_uint(a0[4]);
                        af[im][3] = __float_as_uint(a1[4]);
                    }
#pragma unroll
                    for (int in = 0; in < 4; ++in) {
                        const int n0 = wn * 32 + in * 8;
                        bf[in][0] = __float_as_uint(Bw[(ks + t4) * 132 + n0 + g]);
                        bf[in][1] = __float_as_uint(Bw[(ks + t4 + 4) * 132 + n0 + g]);
                    }
#pragma unroll
                    for (int im = 0; im < 4; ++im)
#pragma unroll
                        for (int in = 0; in < 4; ++in)
                            mma_tf32(acc[im][in], af[im], bf[in]);
                }
            }
            // drain remaining groups before smem reuse by next tile
            asm volatile("cp.async.wait_group 0;\n" ::);

#pragma unroll
            for (int im = 0; im < 4; ++im) {
                const int r0 = rowBase + wm * 64 + im * 16 + g;
#pragma unroll
                for (int in = 0; in < 4; ++in) {
                    const int c0 = nb + wn * 32 + in * 8 + t4 * 2;
#pragma unroll
                    for (int e2 = 0; e2 < 4; ++e2) {
                        const int row = r0 + ((e2 & 2) ? 8 : 0);
                        const int col = c0 + (e2 & 1);
                        if (col < NV) {
                            // T-MAJOR row -> (t, b) -> reference row b*NT+t
                            const int t = row >> 2, b = row & 3;
                            C[((size_t)b * NT + t) * NV + col] =
                                acc[im][in][e2] + bias[col];
                        }
                    }
                }
            }
        }
    }
}

// ---------------------------------------------------------------------------
// Launch
// ---------------------------------------------------------------------------
extern "C" void kernel_launch(void* const* d_in, const int* in_sizes, int n_in,
                              void* d_out, int out_size) {
    const int*   x     = (const int*)  d_in[0];
    const float* embed = (const float*)d_in[1];
    const float* Wx0   = (const float*)d_in[2];
    const float* Wh0   = (const float*)d_in[3];
    const float* b0    = (const float*)d_in[4];
    const float* Wx1   = (const float*)d_in[5];
    const float* Wh1   = (const float*)d_in[6];
    const float* b1    = (const float*)d_in[7];
    const float* Wu    = (const float*)d_in[8];
    const float* bu    = (const float*)d_in[9];
    float* out = (float*)d_out;

    void *pA = nullptr, *pB = nullptr;
    cudaGetSymbolAddress(&pA, g_bufA);
    cudaGetSymbolAddress(&pB, g_bufB);
    float* bufA = (float*)pA;
    float* bufB = (float*)pB;

    cudaFuncSetAttribute(fused_all,
                         cudaFuncAttributeMaxDynamicSharedMemorySize,
                         FUSED_SMEM);

    init_kernel<<<1, 256>>>();
    fused_all<<<GRID_CTAS, 256, FUSED_SMEM>>>(
        x, embed, Wx0, b0, Wh0, Wx1, Wh1, b1, Wu, bu,
        bufA, bufB, out);
}

// round 15
// speedup vs baseline: 1.3831x; 1.3831x over previous
#include <cuda_runtime.h>
#include <cuda_bf16.h>
#include <math.h>
#include <stdint.h>

// ---------------------------------------------------------------------------
// Problem constants
// ---------------------------------------------------------------------------
#define NB   4        // batch
#define NT   1024     // time steps
#define NL   512      // latent / emb
#define NV   50257    // vocab
#define NR   (NB*NT)  // 4096 rows
#define NVP  50304    // padded vocab pitch (= 393*128, 16B-aligned rows)
#define NCT  393      // column tiles in unembed

// big GEMM tiling (cp.async pipelined)
#define UBM 128
#define UBN 128
#define UBK 16
#define UST 4
#define UAS (UBM*20)
#define UBS (UBK*132)
#define FUSED_SMEM (UST*(UAS+UBS)*4)   // 74752 bytes (covers all roles)

#define SCAN_CTAS 64
#define GRID_CTAS 296                  // 2 waves x 148 SMs
#define NQ_XW     128                  // XW0 tiles (8 chunks x 4 b x 4 ct)
#define NQ_UN     (32*NCT)             // 12576 unembed tiles (32 t-groups)
#define NQ_TOT    (NQ_XW + NQ_UN)

// ---------------------------------------------------------------------------
// Scratch (device globals — no allocation allowed)
// ---------------------------------------------------------------------------
__device__ float g_bufA[NR * NL];     // XW0 (= embed[x]@Wx0 + b0), [b][t] rows
__device__ float g_bufB[NR * NL];     // H1, T-MAJOR rows [t][b], tf32-rounded
__device__ float g_wu[NL * NVP];      // Wu, tf32-rounded + padded (on demand)
__device__ float4 g_h0[2][NL];        // depth-2 ring, layer-0 h, [k]={b0..b3}
__device__ float4 g_h1[2][NL];        // depth-2 ring, layer-1 h
__device__ unsigned g_bar;            // scan progress counter (single, proven)
__device__ unsigned g_q;              // work-stealing queue head
__device__ unsigned g_xwcnt[32];      // per-(batch,128-t-chunk) XW0 tile count
__device__ unsigned g_wuflag[NCT];    // per-column-band Wu conversion flag
__device__ unsigned g_smids[SCAN_CTAS];  // scan CTA -> smid+1
__device__ unsigned g_smidcnt;        // #scan CTAs that published smid

// ---------------------------------------------------------------------------
// Helpers
// ---------------------------------------------------------------------------
__device__ __forceinline__ unsigned f2tf32(float f) {
    unsigned u;
    asm("cvt.rna.tf32.f32 %0, %1;" : "=r"(u) : "f"(f));
    return u;
}

__device__ __forceinline__ void mma_tf32(float c[4], const unsigned a[4],
                                         const unsigned b[2]) {
    asm volatile(
        "mma.sync.aligned.m16n8k8.row.col.f32.tf32.tf32.f32 "
        "{%0,%1,%2,%3},{%4,%5,%6,%7},{%8,%9},{%0,%1,%2,%3};"
        : "+f"(c[0]), "+f"(c[1]), "+f"(c[2]), "+f"(c[3])
        : "r"(a[0]), "r"(a[1]), "r"(a[2]), "r"(a[3]), "r"(b[0]), "r"(b[1]));
}

__device__ __forceinline__ void cp16(uint32_t dst, const void* src) {
    asm volatile("cp.async.cg.shared.global [%0], [%1], 16;\n"
                 :: "r"(dst), "l"(src));
}

__device__ __forceinline__ unsigned ld_acq(const unsigned* p) {
    unsigned v;
    asm volatile("ld.acquire.gpu.global.u32 %0, [%1];"
                 : "=r"(v) : "l"(p) : "memory");
    return v;
}

__device__ __forceinline__ void st_rel(unsigned* p, unsigned v) {
    asm volatile("st.release.gpu.global.u32 [%0], %1;"
                 :: "l"(p), "r"(v) : "memory");
}

__device__ __forceinline__ void red_rel(unsigned* p) {
    asm volatile("red.release.gpu.global.add.u32 [%0], %1;"
                 :: "l"(p), "r"(1u) : "memory");
}

// ---------------------------------------------------------------------------
// init: reset all counters + zero both h rings
// ---------------------------------------------------------------------------
__global__ void init_kernel() {
    const int tid = threadIdx.x;
    if (tid == 0) { g_bar = 0u; g_q = 0u; g_smidcnt = 0u; }
    for (int i = tid; i < SCAN_CTAS; i += 256) g_smids[i] = 0u;
    for (int i = tid; i < 32; i += 256) g_xwcnt[i] = 0u;
    for (int i = tid; i < NCT; i += 256) g_wuflag[i] = 0u;
    float4 z = make_float4(0.f, 0.f, 0.f, 0.f);
    for (int i = tid; i < 2 * NL; i += 256) {
        ((float4*)g_h0)[i] = z;
        ((float4*)g_h1)[i] = z;
    }
}

// ---------------------------------------------------------------------------
// FUSED kernel (R13 structure — best measured).
//   bids [0,64):  scan. Single-counter barrier, single poller per CTA, with
//                 nanosleep backoff (cuts hot-line load/red contention).
//                 XW0 prefetched BEFORE the wait except at chunk starts
//                 (chunk gate + syncthreads at e&~127 already ordered it).
//   bids [64,296): workers: self-evict off scan SMs, then steal tiles
//                 (128 XW0 tiles, then 12576 unembed tiles by t-group).
// ---------------------------------------------------------------------------
__global__ __launch_bounds__(256, 2)
void fused_all(const int* __restrict__ x,
               const float* __restrict__ embed,
               const float* __restrict__ Wx0,
               const float* __restrict__ b0,
               const float* __restrict__ Wh0,
               const float* __restrict__ Wx1,
               const float* __restrict__ Wh1,
               const float* __restrict__ b1,
               const float* __restrict__ Wu,
               const float* __restrict__ bias,
               float* __restrict__ XW0,
               float* __restrict__ H1,
               float* __restrict__ C) {
    extern __shared__ float sm[];
    unsigned* const barp = &g_bar;
    const int tid = threadIdx.x;

    if (blockIdx.x < SCAN_CTAS) {
        // ===================== SCAN =====================
        if (tid == 0) {
            unsigned smid;
            asm("mov.u32 %0, %%smid;" : "=r"(smid));
            st_rel(&g_smids[blockIdx.x], smid + 1u);
            red_rel(&g_smidcnt);
        }

        float4* hT0 = (float4*)sm;            // 512
        float4* hT1 = hT0 + 512;              // 512
        float4* sred0 = hT1 + 512;            // [8][4]
        float4* sred1 = sred0 + 32;           // [8][4]

        const int lane = tid & 31;
        const int warp = tid >> 5;
        const int blk  = blockIdx.x;
        const int jw   = blk * 8 + warp;

        float w0[16], w1x[16], w1h[16];
#pragma unroll
        for (int i = 0; i < 16; ++i) {
            const size_t k = (size_t)(lane + 32 * i) * NL + jw;
            w0[i]  = Wh0[k];
            w1x[i] = Wx1[k];
            w1h[i] = Wh1[k];
        }
        const float bias1 = (lane >= 4 && lane < 8) ? b1[jw] : 0.f;
        const int i0 = tid, i1 = tid + 256;

        for (int e = 0; e <= NT; ++e) {
            const bool do0 = (e < NT);
            const bool do1 = (e >= 1);
            const bool chunk_start = do0 && ((e & 127) == 0);

            // XW0 prefetch BEFORE the wait (safe off chunk starts: the gate
            // at epoch e&~127 + its syncthreads ordered these producers).
            float xw = 0.f;
            if (do0 && !chunk_start && lane < 4)
                xw = __ldcg(&XW0[((size_t)lane * NT + e) * NL + jw]);

            if (tid == 0) {
                if (chunk_start) {
                    const int c = e >> 7;
                    for (int b = 0; b < 4; ++b)
                        while (ld_acq(&g_xwcnt[b * 8 + c]) < 4u)
                            __nanosleep(64);
                }
                if (e > 0) {
                    const unsigned tgt = 64u * (unsigned)e;
                    while (ld_acq(barp) < tgt) __nanosleep(32);
                }
            }
            __syncthreads();

            if (chunk_start && lane < 4)
                xw = __ldcg(&XW0[((size_t)lane * NT + e) * NL + jw]);

            hT0[i0] = __ldcg(&g_h0[(e + 1) & 1][i0]);
            hT0[i1] = __ldcg(&g_h0[(e + 1) & 1][i1]);
            if (do1) {
                hT1[i0] = __ldcg(&g_h1[e & 1][i0]);
                hT1[i1] = __ldcg(&g_h1[e & 1][i1]);
            }
            __syncthreads();

            float ax = 0.f, ay = 0.f, az = 0.f, aw = 0.f;
            float bx = 0.f, by = 0.f, bz = 0.f, bw = 0.f;
#pragma unroll
            for (int i = 0; i < 16; ++i) {
                const float4 hv = hT0[lane + 32 * i];
                const float wa = w0[i];
                const float wb = w1x[i];
                ax = fmaf(wa, hv.x, ax);
                ay = fmaf(wa, hv.y, ay);
                az = fmaf(wa, hv.z, az);
                aw = fmaf(wa, hv.w, aw);
                bx = fmaf(wb, hv.x, bx);
                by = fmaf(wb, hv.y, by);
                bz = fmaf(wb, hv.z, bz);
                bw = fmaf(wb, hv.w, bw);
            }
            if (do1) {
#pragma unroll
                for (int i = 0; i < 16; ++i) {
                    const float4 hv = hT1[lane + 32 * i];
                    const float wb = w1h[i];
                    bx = fmaf(wb, hv.x, bx);
                    by = fmaf(wb, hv.y, by);
                    bz = fmaf(wb, hv.z, bz);
                    bw = fmaf(wb, hv.w, bw);
                }
            }

#pragma unroll
            for (int off = 16; off >= 4; off >>= 1) {
                ax += __shfl_down_sync(0xffffffffu, ax, off);
                ay += __shfl_down_sync(0xffffffffu, ay, off);
                az += __shfl_down_sync(0xffffffffu, az, off);
                aw += __shfl_down_sync(0xffffffffu, aw, off);
                bx += __shfl_down_sync(0xffffffffu, bx, off);
                by += __shfl_down_sync(0xffffffffu, by, off);
                bz += __shfl_down_sync(0xffffffffu, bz, off);
                bw += __shfl_down_sync(0xffffffffu, bw, off);
            }
            if (lane < 4) {
                sred0[warp * 4 + lane] = make_float4(ax, ay, az, aw);
                sred1[warp * 4 + lane] = make_float4(bx, by, bz, bw);
            }
            __syncwarp();

            if (do0 && lane < 4) {
                const float* p = (const float*)&sred0[warp * 4];
                const float s = p[lane] + p[4 + lane] + p[8 + lane] + p[12 + lane];
                const float hn = tanhf(s + xw);
                __stcg(&((float*)&g_h0[e & 1][jw])[lane], hn);
            }
            if (do1 && lane >= 4 && lane < 8) {
                const int b = lane - 4;
                const float* p = (const float*)&sred1[warp * 4];
                const float s = p[b] + p[4 + b] + p[8 + b] + p[12 + b];
                const float hn = tanhf(s + bias1);
                __stcg(&((float*)&g_h1[(e + 1) & 1][jw])[b], hn);
                // T-MAJOR: row = t*4 + b  (t = e-1)
                H1[((size_t)(e - 1) * 4 + b) * NL + jw] =
                    __uint_as_float(f2tf32(hn));
            }

            __syncthreads();   // CTA-wide HB edge: writes -> tid0's release
            if (tid == 0) red_rel(barp);
        }
        return;
    }

    // ===================== WORKER =====================
    __shared__ unsigned s_exit, s_tile;

    if (tid == 0) {
        unsigned mysm;
        asm("mov.u32 %0, %%smid;" : "=r"(mysm));
        while (ld_acq(&g_smidcnt) < (unsigned)SCAN_CTAS) { }
        unsigned ex = 0u;
        for (int i = 0; i < SCAN_CTAS; ++i)
            if (ld_acq(&g_smids[i]) == mysm + 1u) { ex = 1u; break; }
        s_exit = ex;
    }
    __syncthreads();
    if (s_exit) return;   // leave the scan CTA alone on this SM

    const int lane = tid & 31;
    const int warp = tid >> 5;
    const int wm = warp & 1;
    const int wn = warp >> 1;
    const int g  = lane >> 2;
    const int t4 = lane & 3;

    for (;;) {
        __syncthreads();
        if (tid == 0) s_tile = atomicAdd(&g_q, 1u);
        __syncthreads();
        const unsigned tile = s_tile;
        if (tile >= (unsigned)NQ_TOT) return;

        if (tile < (unsigned)NQ_XW) {
            // ---------- XW0 GEMM tile (chunk-ordered) ----------
            const int uid2 = (int)tile;
            const int c  = uid2 >> 4;
            const int b  = (uid2 >> 2) & 3;
            const int ct = uid2 & 3;
            const int rowBase = b * 1024 + c * 128;
            const int nb = ct * 128;
            const int rt = b * 8 + c;

            float* As = sm;                 // [2][128][20]
            float* Bs = sm + 2 * 128 * 20;  // [2][16][132]

            float acc[4][4][4];
#pragma unroll
            for (int a = 0; a < 4; ++a)
#pragma unroll
                for (int b2 = 0; b2 < 4; ++b2)
#pragma unroll
                    for (int e2 = 0; e2 < 4; ++e2) acc[a][b2][e2] = 0.f;

            const int ar0 = tid >> 2, af0 = tid & 3;
            const int ar1 = (tid + 256) >> 2;
            const float* arow0 = embed + (size_t)x[rowBase + ar0] * NL;
            const float* arow1 = embed + (size_t)x[rowBase + ar1] * NL;
            const int bk0 = tid >> 5, bc = tid & 31;
            const int bk1 = bk0 + 8;

            float4 pa0 = *(const float4*)(arow0 + af0 * 4);
            float4 pa1 = *(const float4*)(arow1 + af0 * 4);
            float4 pb0 = *(const float4*)(Wx0 + (size_t)bk0 * NL + nb + bc * 4);
            float4 pb1 = *(const float4*)(Wx0 + (size_t)bk1 * NL + nb + bc * 4);

            int w = 0;
            for (int kb = 0; kb < NL; kb += UBK) {
                {
                    float4 v;
                    v.x = __uint_as_float(f2tf32(pa0.x));
                    v.y = __uint_as_float(f2tf32(pa0.y));
                    v.z = __uint_as_float(f2tf32(pa0.z));
                    v.w = __uint_as_float(f2tf32(pa0.w));
                    *(float4*)&As[w * (128 * 20) + ar0 * 20 + af0 * 4] = v;
                    v.x = __uint_as_float(f2tf32(pa1.x));
                    v.y = __uint_as_float(f2tf32(pa1.y));
                    v.z = __uint_as_float(f2tf32(pa1.z));
                    v.w = __uint_as_float(f2tf32(pa1.w));
                    *(float4*)&As[w * (128 * 20) + ar1 * 20 + af0 * 4] = v;
                    v.x = __uint_as_float(f2tf32(pb0.x));
                    v.y = __uint_as_float(f2tf32(pb0.y));
                    v.z = __uint_as_float(f2tf32(pb0.z));
                    v.w = __uint_as_float(f2tf32(pb0.w));
                    *(float4*)&Bs[w * (16 * 132) + bk0 * 132 + bc * 4] = v;
                    v.x = __uint_as_float(f2tf32(pb1.x));
                    v.y = __uint_as_float(f2tf32(pb1.y));
                    v.z = __uint_as_float(f2tf32(pb1.z));
                    v.w = __uint_as_float(f2tf32(pb1.w));
                    *(float4*)&Bs[w * (16 * 132) + bk1 * 132 + bc * 4] = v;
                }
                __syncthreads();

                if (kb + UBK < NL) {
                    pa0 = *(const float4*)(arow0 + kb + UBK + af0 * 4);
                    pa1 = *(const float4*)(arow1 + kb + UBK + af0 * 4);
                    pb0 = *(const float4*)(Wx0 + (size_t)(kb + UBK + bk0) * NL + nb + bc * 4);
                    pb1 = *(const float4*)(Wx0 + (size_t)(kb + UBK + bk1) * NL + nb + bc * 4);
                }

                const float* Aw = &As[w * (128 * 20)];
                const float* Bw = &Bs[w * (16 * 132)];
#pragma unroll
                for (int ks = 0; ks < UBK; ks += 8) {
                    unsigned af[4][4], bf[4][2];
#pragma unroll
                    for (int im = 0; im < 4; ++im) {
                        const int m0 = wm * 64 + im * 16;
                        const float* a0 = Aw + (m0 + g) * 20 + ks + t4;
                        const float* a1 = Aw + (m0 + g + 8) * 20 + ks + t4;
                        af[im][0] = __float_as_uint(a0[0]);
                        af[im][1] = __float_as_uint(a1[0]);
                        af[im][2] = __float_as_uint(a0[4]);
                        af[im][3] = __float_as_uint(a1[4]);
                    }
#pragma unroll
                    for (int in = 0; in < 4; ++in) {
                        const int n0 = wn * 32 + in * 8;
                        bf[in][0] = __float_as_uint(Bw[(ks + t4) * 132 + n0 + g]);
                        bf[in][1] = __float_as_uint(Bw[(ks + t4 + 4) * 132 + n0 + g]);
                    }
#pragma unroll
                    for (int im = 0; im < 4; ++im)
#pragma unroll
                        for (int in = 0; in < 4; ++in)
                            mma_tf32(acc[im][in], af[im], bf[in]);
                }
                w ^= 1;
                __syncthreads();
            }

#pragma unroll
            for (int im = 0; im < 4; ++im) {
                const int r0 = rowBase + wm * 64 + im * 16 + g;
#pragma unroll
                for (int in = 0; in < 4; ++in) {
                    const int c0 = nb + wn * 32 + in * 8 + t4 * 2;
#pragma unroll
                    for (int e2 = 0; e2 < 4; ++e2) {
                        const int row = r0 + ((e2 & 2) ? 8 : 0);
                        const int col = c0 + (e2 & 1);
                        XW0[(size_t)row * NL + col] = acc[im][in][e2] + b0[col];
                    }
                }
            }
            __syncthreads();
            if (tid == 0) red_rel(&g_xwcnt[rt]);
        } else {
            // ---------- UNEMBED tile (32-step t-group granularity) ----------
            const int u  = (int)(tile - NQ_XW);
            const int jj = u / NCT;               // t-group 0..31
            const int xq = u % NCT;               // column tile 0..392
            const int rowBase = jj * 128;         // T-MAJOR rows
            const int nb      = xq * UBN;

            if (jj == 0) {
                // CONVERT band xq: g_wu[k][nb..nb+128) = tf32(Wu)
                for (int idx = tid; idx < NL * UBN; idx += 256) {
                    const int k = idx >> 7;
                    const int n = nb + (idx & 127);
                    g_wu[(size_t)k * NVP + n] =
                        (n < NV) ? __uint_as_float(f2tf32(Wu[(size_t)k * NV + n]))
                                 : 0.f;
                }
                __syncthreads();
                if (tid == 0) red_rel(&g_wuflag[xq]);
            } else {
                if (tid == 0)
                    while (ld_acq(&g_wuflag[xq]) < 1u) __nanosleep(128);
            }

            // H1 rows cover t in [32jj, 32jj+32): counter >= 64*(32*(jj+1)+1)
            const unsigned tgt = 64u * (unsigned)(32 * (jj + 1) + 1);
            if (tid == 0)
                while (ld_acq(barp) < tgt) __nanosleep(256);
            __syncthreads();

            const float* A = H1;
            const uint32_t smem_u32 = (uint32_t)__cvta_generic_to_shared(sm);

            float acc[4][4][4];
#pragma unroll
            for (int a = 0; a < 4; ++a)
#pragma unroll
                for (int b2 = 0; b2 < 4; ++b2)
#pragma unroll
                    for (int e2 = 0; e2 < 4; ++e2) acc[a][b2][e2] = 0.f;

            const int arow = tid >> 2;
            const int ac4  = tid & 3;
            const float* aptr0 = A + (size_t)(rowBase + arow) * NL + ac4 * 4;
            const float* aptr1 = A + (size_t)(rowBase + arow + 64) * NL + ac4 * 4;
            const int bkr0 = tid >> 5;
            const int bc0  = tid & 31;
            const float* bptr0 = g_wu + (size_t)bkr0 * NVP + nb + bc0 * 4;
            const float* bptr1 = g_wu + (size_t)(bkr0 + 8) * NVP + nb + bc0 * 4;

            const uint32_t adst0 = smem_u32 + (arow * 20 + ac4 * 4) * 4;
            const uint32_t adst1 = smem_u32 + ((arow + 64) * 20 + ac4 * 4) * 4;
            const uint32_t bdst0 = smem_u32 + (UST * UAS + bkr0 * 132 + bc0 * 4) * 4;
            const uint32_t bdst1 = smem_u32 + (UST * UAS + (bkr0 + 8) * 132 + bc0 * 4) * 4;

            const int NKT = NL / UBK;

#pragma unroll
            for (int s = 0; s < UST - 1; ++s) {
                const int kb = s * UBK;
                cp16(adst0 + s * UAS * 4, aptr0 + kb);
                cp16(adst1 + s * UAS * 4, aptr1 + kb);
                cp16(bdst0 + s * UBS * 4, bptr0 + (size_t)kb * NVP);
                cp16(bdst1 + s * UBS * 4, bptr1 + (size_t)kb * NVP);
                asm volatile("cp.async.commit_group;\n" ::);
            }

            for (int kt = 0; kt < NKT; ++kt) {
                asm volatile("cp.async.wait_group 2;\n" ::);
                __syncthreads();

                if (kt + UST - 1 < NKT) {
                    const int s  = (kt + UST - 1) & (UST - 1);
                    const int kb = (kt + UST - 1) * UBK;
                    cp16(adst0 + s * UAS * 4, aptr0 + kb);
                    cp16(adst1 + s * UAS * 4, aptr1 + kb);
                    cp16(bdst0 + s * UBS * 4, bptr0 + (size_t)kb * NVP);
                    cp16(bdst1 + s * UBS * 4, bptr1 + (size_t)kb * NVP);
                }
                asm volatile("cp.async.commit_group;\n" ::);

                const float* Aw = sm + (kt & (UST - 1)) * UAS;
                const float* Bw = sm + UST * UAS + (kt & (UST - 1)) * UBS;
#pragma unroll
                for (int ks = 0; ks < UBK; ks += 8) {
                    unsigned af[4][4], bf[4][2];
#pragma unroll
                    for (int im = 0; im < 4; ++im) {
                        const int m0 = wm * 64 + im * 16;
                        const float* a0 = Aw + (m0 + g) * 20 + ks + t4;
                        const float* a1 = Aw + (m0 + g + 8) * 20 + ks + t4;
                        af[im][0] = __float_as_uint(a0[0]);
                        af[im][1] = __float_as_uint(a1[0]);
                        af[im][2] = __float_as_uint(a0[4]);
                        af[im][3] = __float_as_uint(a1[4]);
                    }
#pragma unroll
                    for (int in = 0; in < 4; ++in) {
                        const int n0 = wn * 32 + in * 8;
                        bf[in][0] = __float_as_uint(Bw[(ks + t4) * 132 + n0 + g]);
                        bf[in][1] = __float_as_uint(Bw[(ks + t4 + 4) * 132 + n0 + g]);
                    }
#pragma unroll
                    for (int im = 0; im < 4; ++im)
#pragma unroll
                        for (int in = 0; in < 4; ++in)
                            mma_tf32(acc[im][in], af[im], bf[in]);
                }
            }
            // drain remaining groups before smem reuse by next tile
            asm volatile("cp.async.wait_group 0;\n" ::);

#pragma unroll
            for (int im = 0; im < 4; ++im) {
                const int r0 = rowBase + wm * 64 + im * 16 + g;
#pragma unroll
                for (int in = 0; in < 4; ++in) {
                    const int c0 = nb + wn * 32 + in * 8 + t4 * 2;
#pragma unroll
                    for (int e2 = 0; e2 < 4; ++e2) {
                        const int row = r0 + ((e2 & 2) ? 8 : 0);
                        const int col = c0 + (e2 & 1);
                        if (col < NV) {
                            // T-MAJOR row -> (t, b) -> reference row b*NT+t
                            const int t = row >> 2, b = row & 3;
                            C[((size_t)b * NT + t) * NV + col] =
                                acc[im][in][e2] + bias[col];
                        }
                    }
                }
            }
        }
    }
}

// ---------------------------------------------------------------------------
// Launch
// ---------------------------------------------------------------------------
extern "C" void kernel_launch(void* const* d_in, const int* in_sizes, int n_in,
                              void* d_out, int out_size) {
    const int*   x     = (const int*)  d_in[0];
    const float* embed = (const float*)d_in[1];
    const float* Wx0   = (const float*)d_in[2];
    const float* Wh0   = (const float*)d_in[3];
    const float* b0    = (const float*)d_in[4];
    const float* Wx1   = (const float*)d_in[5];
    const float* Wh1   = (const float*)d_in[6];
    const float* b1    = (const float*)d_in[7];
    const float* Wu    = (const float*)d_in[8];
    const float* bu    = (const float*)d_in[9];
    float* out = (float*)d_out;

    void *pA = nullptr, *pB = nullptr;
    cudaGetSymbolAddress(&pA, g_bufA);
    cudaGetSymbolAddress(&pB, g_bufB);
    float* bufA = (float*)pA;
    float* bufB = (float*)pB;

    cudaFuncSetAttribute(fused_all,
                         cudaFuncAttributeMaxDynamicSharedMemorySize,
                         FUSED_SMEM);

    init_kernel<<<1, 256>>>();
    fused_all<<<GRID_CTAS, 256, FUSED_SMEM>>>(
        x, embed, Wx0, b0, Wh0, Wx1, Wh1, b1, Wu, bu,
        bufA, bufB, out);
}

// round 16
// speedup vs baseline: 1.3989x; 1.0115x over previous
#include <cuda_runtime.h>
#include <cuda_bf16.h>
#include <math.h>
#include <stdint.h>

// ---------------------------------------------------------------------------
// Problem constants
// ---------------------------------------------------------------------------
#define NB   4        // batch
#define NT   1024     // time steps
#define NL   512      // latent / emb
#define NV   50257    // vocab
#define NR   (NB*NT)  // 4096 rows
#define NVP  50304    // padded vocab pitch (= 393*128, 16B-aligned rows)
#define NCT  393      // column tiles in unembed

// big GEMM tiling (cp.async pipelined)
#define UBM 128
#define UBN 128
#define UBK 16
#define UST 4
#define UAS (UBM*20)
#define UBS (UBK*132)
#define FUSED_SMEM (UST*(UAS+UBS)*4)   // 74752 bytes (covers all roles)

#define SCAN_CTAS 32                   // 32 scan CTAs x 512 threads
#define SCAN_THR  512
#define GRID_CTAS 296                  // 2 waves x 148 SMs
#define NQ_XW     128                  // XW0 tiles (8 chunks x 4 b x 4 ct)
#define NQ_UN     (32*NCT)             // 12576 unembed tiles (32 t-groups)
#define NQ_TOT    (NQ_XW + NQ_UN)

// ---------------------------------------------------------------------------
// Scratch (device globals — no allocation allowed)
// ---------------------------------------------------------------------------
__device__ float g_bufA[NR * NL];     // XW0 (= embed[x]@Wx0 + b0), [b][t] rows
__device__ float g_bufB[NR * NL];     // H1, T-MAJOR rows [t][b], tf32-rounded
__device__ float g_wu[NL * NVP];      // Wu, tf32-rounded + padded (on demand)
__device__ float4 g_h0[2][NL];        // depth-2 ring, layer-0 h, [k]={b0..b3}
__device__ float4 g_h1[2][NL];        // depth-2 ring, layer-1 h
__device__ unsigned g_bar;            // scan progress counter (single, proven)
__device__ unsigned g_q;              // work-stealing queue head
__device__ unsigned g_xwcnt[32];      // per-(batch,128-t-chunk) XW0 tile count
__device__ unsigned g_wuflag[NCT];    // per-column-band Wu conversion flag
__device__ unsigned g_smids[SCAN_CTAS];  // scan CTA -> smid+1
__device__ unsigned g_smidcnt;        // #scan CTAs that published smid

// ---------------------------------------------------------------------------
// Helpers
// ---------------------------------------------------------------------------
__device__ __forceinline__ unsigned f2tf32(float f) {
    unsigned u;
    asm("cvt.rna.tf32.f32 %0, %1;" : "=r"(u) : "f"(f));
    return u;
}

__device__ __forceinline__ void mma_tf32(float c[4], const unsigned a[4],
                                         const unsigned b[2]) {
    asm volatile(
        "mma.sync.aligned.m16n8k8.row.col.f32.tf32.tf32.f32 "
        "{%0,%1,%2,%3},{%4,%5,%6,%7},{%8,%9},{%0,%1,%2,%3};"
        : "+f"(c[0]), "+f"(c[1]), "+f"(c[2]), "+f"(c[3])
        : "r"(a[0]), "r"(a[1]), "r"(a[2]), "r"(a[3]), "r"(b[0]), "r"(b[1]));
}

__device__ __forceinline__ void cp16(uint32_t dst, const void* src) {
    asm volatile("cp.async.cg.shared.global [%0], [%1], 16;\n"
                 :: "r"(dst), "l"(src));
}

__device__ __forceinline__ unsigned ld_acq(const unsigned* p) {
    unsigned v;
    asm volatile("ld.acquire.gpu.global.u32 %0, [%1];"
                 : "=r"(v) : "l"(p) : "memory");
    return v;
}

__device__ __forceinline__ void st_rel(unsigned* p, unsigned v) {
    asm volatile("st.release.gpu.global.u32 [%0], %1;"
                 :: "l"(p), "r"(v) : "memory");
}

__device__ __forceinline__ void red_rel(unsigned* p) {
    asm volatile("red.release.gpu.global.add.u32 [%0], %1;"
                 :: "l"(p), "r"(1u) : "memory");
}

// ---------------------------------------------------------------------------
// init: reset all counters + zero both h rings
// ---------------------------------------------------------------------------
__global__ void init_kernel() {
    const int tid = threadIdx.x;
    if (tid == 0) { g_bar = 0u; g_q = 0u; g_smidcnt = 0u; }
    for (int i = tid; i < SCAN_CTAS; i += 256) g_smids[i] = 0u;
    for (int i = tid; i < 32; i += 256) g_xwcnt[i] = 0u;
    for (int i = tid; i < NCT; i += 256) g_wuflag[i] = 0u;
    float4 z = make_float4(0.f, 0.f, 0.f, 0.f);
    for (int i = tid; i < 2 * NL; i += 256) {
        ((float4*)g_h0)[i] = z;
        ((float4*)g_h1)[i] = z;
    }
}

// ---------------------------------------------------------------------------
// FUSED kernel.
//   bids [0,32):  scan. 32 CTAs x 512 thr (16 warps, warp-per-column).
//                 Single-counter barrier, single poller, backoff poll.
//                 XW0 prefetched before the wait off chunk starts.
//   bids [32,296): workers: self-evict off scan SMs, then steal tiles.
//                 C stores use __stcs (evict-first) to cut L2 pollution.
//   Block size is 512; workers use threads 0..255 for GEMM roles and keep
//   threads 256..511 co-running the same code paths (all loops are
//   tid-strided over 512 where it matters; GEMM lanes are tid<512-safe
//   by construction: roles computed from tid over 512 threads).
// ---------------------------------------------------------------------------
__global__ __launch_bounds__(SCAN_THR, 1)
void fused_all(const int* __restrict__ x,
               const float* __restrict__ embed,
               const float* __restrict__ Wx0,
               const float* __restrict__ b0,
               const float* __restrict__ Wh0,
               const float* __restrict__ Wx1,
               const float* __restrict__ Wh1,
               const float* __restrict__ b1,
               const float* __restrict__ Wu,
               const float* __restrict__ bias,
               float* __restrict__ XW0,
               float* __restrict__ H1,
               float* __restrict__ C) {
    extern __shared__ float sm[];
    unsigned* const barp = &g_bar;
    const int tid = threadIdx.x;

    if (blockIdx.x < SCAN_CTAS) {
        // ===================== SCAN (32 CTAs x 512 thr) =====================
        if (tid == 0) {
            unsigned smid;
            asm("mov.u32 %0, %%smid;" : "=r"(smid));
            st_rel(&g_smids[blockIdx.x], smid + 1u);
            red_rel(&g_smidcnt);
        }

        float4* hT0 = (float4*)sm;            // 512
        float4* hT1 = hT0 + 512;              // 512
        float4* sred0 = hT1 + 512;            // [16][4]
        float4* sred1 = sred0 + 64;           // [16][4]

        const int lane = tid & 31;
        const int warp = tid >> 5;            // 0..15
        const int blk  = blockIdx.x;          // 0..31
        const int jw   = blk * 16 + warp;     // this warp's column

        float w0[16], w1x[16], w1h[16];
#pragma unroll
        for (int i = 0; i < 16; ++i) {
            const size_t k = (size_t)(lane + 32 * i) * NL + jw;
            w0[i]  = Wh0[k];
            w1x[i] = Wx1[k];
            w1h[i] = Wh1[k];
        }
        const float bias1 = (lane >= 4 && lane < 8) ? b1[jw] : 0.f;

        for (int e = 0; e <= NT; ++e) {
            const bool do0 = (e < NT);
            const bool do1 = (e >= 1);
            const bool chunk_start = do0 && ((e & 127) == 0);

            // XW0 prefetch BEFORE the wait (safe off chunk starts: the gate
            // at epoch e&~127 + its syncthreads ordered these producers).
            float xw = 0.f;
            if (do0 && !chunk_start && lane < 4)
                xw = __ldcg(&XW0[((size_t)lane * NT + e) * NL + jw]);

            if (tid == 0) {
                if (chunk_start) {
                    const int c = e >> 7;
                    for (int b = 0; b < 4; ++b)
                        while (ld_acq(&g_xwcnt[b * 8 + c]) < 4u)
                            __nanosleep(64);
                }
                if (e > 0) {
                    const unsigned tgt = (unsigned)SCAN_CTAS * (unsigned)e;
                    while (ld_acq(barp) < tgt) __nanosleep(32);
                }
            }
            __syncthreads();

            if (chunk_start && lane < 4)
                xw = __ldcg(&XW0[((size_t)lane * NT + e) * NL + jw]);

            // stage h (512 threads -> one h0 + one h1 element each)
            hT0[tid] = __ldcg(&g_h0[(e + 1) & 1][tid]);
            if (do1) hT1[tid] = __ldcg(&g_h1[e & 1][tid]);
            __syncthreads();

            float ax = 0.f, ay = 0.f, az = 0.f, aw = 0.f;
            float bx = 0.f, by = 0.f, bz = 0.f, bw = 0.f;
#pragma unroll
            for (int i = 0; i < 16; ++i) {
                const float4 hv = hT0[lane + 32 * i];
                const float wa = w0[i];
                const float wb = w1x[i];
                ax = fmaf(wa, hv.x, ax);
                ay = fmaf(wa, hv.y, ay);
                az = fmaf(wa, hv.z, az);
                aw = fmaf(wa, hv.w, aw);
                bx = fmaf(wb, hv.x, bx);
                by = fmaf(wb, hv.y, by);
                bz = fmaf(wb, hv.z, bz);
                bw = fmaf(wb, hv.w, bw);
            }
            if (do1) {
#pragma unroll
                for (int i = 0; i < 16; ++i) {
                    const float4 hv = hT1[lane + 32 * i];
                    const float wb = w1h[i];
                    bx = fmaf(wb, hv.x, bx);
                    by = fmaf(wb, hv.y, by);
                    bz = fmaf(wb, hv.z, bz);
                    bw = fmaf(wb, hv.w, bw);
                }
            }

#pragma unroll
            for (int off = 16; off >= 4; off >>= 1) {
                ax += __shfl_down_sync(0xffffffffu, ax, off);
                ay += __shfl_down_sync(0xffffffffu, ay, off);
                az += __shfl_down_sync(0xffffffffu, az, off);
                aw += __shfl_down_sync(0xffffffffu, aw, off);
                bx += __shfl_down_sync(0xffffffffu, bx, off);
                by += __shfl_down_sync(0xffffffffu, by, off);
                bz += __shfl_down_sync(0xffffffffu, bz, off);
                bw += __shfl_down_sync(0xffffffffu, bw, off);
            }
            if (lane < 4) {
                sred0[warp * 4 + lane] = make_float4(ax, ay, az, aw);
                sred1[warp * 4 + lane] = make_float4(bx, by, bz, bw);
            }
            __syncwarp();

            if (do0 && lane < 4) {
                const float* p = (const float*)&sred0[warp * 4];
                const float s = p[lane] + p[4 + lane] + p[8 + lane] + p[12 + lane];
                const float hn = tanhf(s + xw);
                __stcg(&((float*)&g_h0[e & 1][jw])[lane], hn);
            }
            if (do1 && lane >= 4 && lane < 8) {
                const int b = lane - 4;
                const float* p = (const float*)&sred1[warp * 4];
                const float s = p[b] + p[4 + b] + p[8 + b] + p[12 + b];
                const float hn = tanhf(s + bias1);
                __stcg(&((float*)&g_h1[(e + 1) & 1][jw])[b], hn);
                // T-MAJOR: row = t*4 + b  (t = e-1)
                H1[((size_t)(e - 1) * 4 + b) * NL + jw] =
                    __uint_as_float(f2tf32(hn));
            }

            __syncthreads();   // CTA-wide HB edge: writes -> tid0's release
            if (tid == 0) red_rel(barp);
        }
        return;
    }

    // ===================== WORKER (512 thr; GEMM uses 256-role mapping
    //                      over tid&255 with the upper half mirroring) ======
    __shared__ unsigned s_exit, s_tile;

    if (tid == 0) {
        unsigned mysm;
        asm("mov.u32 %0, %%smid;" : "=r"(mysm));
        while (ld_acq(&g_smidcnt) < (unsigned)SCAN_CTAS) { }
        unsigned ex = 0u;
        for (int i = 0; i < SCAN_CTAS; ++i)
            if (ld_acq(&g_smids[i]) == mysm + 1u) { ex = 1u; break; }
        s_exit = ex;
    }
    __syncthreads();
    if (s_exit) return;   // leave the scan CTA alone on this SM

    // 512-thread GEMM role mapping: 16 warps = 2 halves of 8 warps; halves
    // split the M dimension (half 0 -> rows 0..63, half 1 -> rows 64..127
    // of the 128-row tile), each half is the former 8-warp layout.
    const int lane = tid & 31;
    const int warp = tid >> 5;          // 0..15
    const int half = warp >> 3;         // 0..1 (M half)
    const int w8   = warp & 7;          // role within half
    const int wm = half;                // M: 0..1 (64 rows each)
    const int wn = w8 >> 1;             // N: 0..3
    const int ws = w8 & 1;              // sub-M within half: 0..1 (32 rows)
    const int g  = lane >> 2;
    const int t4 = lane & 3;

    for (;;) {
        __syncthreads();
        if (tid == 0) s_tile = atomicAdd(&g_q, 1u);
        __syncthreads();
        const unsigned tile = s_tile;
        if (tile >= (unsigned)NQ_TOT) return;

        if (tile < (unsigned)NQ_XW) {
            // ---------- XW0 GEMM tile (chunk-ordered) ----------
            const int uid2 = (int)tile;
            const int c  = uid2 >> 4;
            const int b  = (uid2 >> 2) & 3;
            const int ct = uid2 & 3;
            const int rowBase = b * 1024 + c * 128;
            const int nb = ct * 128;
            const int rt = b * 8 + c;

            float* As = sm;                 // [2][128][20]
            float* Bs = sm + 2 * 128 * 20;  // [2][16][132]

            // 2 sub-tiles of 32x32 per warp (M: wm*64+ws*32, N: wn*32)
            float acc[2][4][4];
#pragma unroll
            for (int a = 0; a < 2; ++a)
#pragma unroll
                for (int b2 = 0; b2 < 4; ++b2)
#pragma unroll
                    for (int e2 = 0; e2 < 4; ++e2) acc[a][b2][e2] = 0.f;

            // loads: 512 threads, A tile 128x16 = 512 float4 (1 each),
            // B tile 16x128 = 512 float4 (1 each)
            const int ar0 = tid >> 2, af0 = tid & 3;
            const float* arow0 = embed + (size_t)x[rowBase + ar0] * NL;
            const int bk0 = tid >> 5, bc = tid & 31;

            float4 pa0 = *(const float4*)(arow0 + af0 * 4);
            float4 pb0 = *(const float4*)(Wx0 + (size_t)bk0 * NL + nb + bc * 4);

            int w = 0;
            for (int kb = 0; kb < NL; kb += UBK) {
                {
                    float4 v;
                    v.x = __uint_as_float(f2tf32(pa0.x));
                    v.y = __uint_as_float(f2tf32(pa0.y));
                    v.z = __uint_as_float(f2tf32(pa0.z));
                    v.w = __uint_as_float(f2tf32(pa0.w));
                    *(float4*)&As[w * (128 * 20) + ar0 * 20 + af0 * 4] = v;
                    v.x = __uint_as_float(f2tf32(pb0.x));
                    v.y = __uint_as_float(f2tf32(pb0.y));
                    v.z = __uint_as_float(f2tf32(pb0.z));
                    v.w = __uint_as_float(f2tf32(pb0.w));
                    *(float4*)&Bs[w * (16 * 132) + bk0 * 132 + bc * 4] = v;
                }
                __syncthreads();

                if (kb + UBK < NL) {
                    pa0 = *(const float4*)(arow0 + kb + UBK + af0 * 4);
                    pb0 = *(const float4*)(Wx0 + (size_t)(kb + UBK + bk0) * NL + nb + bc * 4);
                }

                const float* Aw = &As[w * (128 * 20)];
                const float* Bw = &Bs[w * (16 * 132)];
#pragma unroll
                for (int ks = 0; ks < UBK; ks += 8) {
                    unsigned af[2][4], bf[4][2];
#pragma unroll
                    for (int im = 0; im < 2; ++im) {
                        const int m0 = wm * 64 + ws * 32 + im * 16;
                        const float* a0 = Aw + (m0 + g) * 20 + ks + t4;
                        const float* a1 = Aw + (m0 + g + 8) * 20 + ks + t4;
                        af[im][0] = __float_as_uint(a0[0]);
                        af[im][1] = __float_as_uint(a1[0]);
                        af[im][2] = __float_as_uint(a0[4]);
                        af[im][3] = __float_as_uint(a1[4]);
                    }
#pragma unroll
                    for (int in = 0; in < 4; ++in) {
                        const int n0 = wn * 32 + in * 8;
                        bf[in][0] = __float_as_uint(Bw[(ks + t4) * 132 + n0 + g]);
                        bf[in][1] = __float_as_uint(Bw[(ks + t4 + 4) * 132 + n0 + g]);
                    }
#pragma unroll
                    for (int im = 0; im < 2; ++im)
#pragma unroll
                        for (int in = 0; in < 4; ++in)
                            mma_tf32(acc[im][in], af[im], bf[in]);
                }
                w ^= 1;
                __syncthreads();
            }

#pragma unroll
            for (int im = 0; im < 2; ++im) {
                const int r0 = rowBase + wm * 64 + ws * 32 + im * 16 + g;
#pragma unroll
                for (int in = 0; in < 4; ++in) {
                    const int c0 = nb + wn * 32 + in * 8 + t4 * 2;
#pragma unroll
                    for (int e2 = 0; e2 < 4; ++e2) {
                        const int row = r0 + ((e2 & 2) ? 8 : 0);
                        const int col = c0 + (e2 & 1);
                        XW0[(size_t)row * NL + col] = acc[im][in][e2] + b0[col];
                    }
                }
            }
            __syncthreads();
            if (tid == 0) red_rel(&g_xwcnt[rt]);
        } else {
            // ---------- UNEMBED tile (32-step t-group granularity) ----------
            const int u  = (int)(tile - NQ_XW);
            const int jj = u / NCT;               // t-group 0..31
            const int xq = u % NCT;               // column tile 0..392
            const int rowBase = jj * 128;         // T-MAJOR rows
            const int nb      = xq * UBN;

            if (jj == 0) {
                // CONVERT band xq: g_wu[k][nb..nb+128) = tf32(Wu)
                for (int idx = tid; idx < NL * UBN; idx += SCAN_THR) {
                    const int k = idx >> 7;
                    const int n = nb + (idx & 127);
                    g_wu[(size_t)k * NVP + n] =
                        (n < NV) ? __uint_as_float(f2tf32(Wu[(size_t)k * NV + n]))
                                 : 0.f;
                }
                __syncthreads();
                if (tid == 0) red_rel(&g_wuflag[xq]);
            } else {
                if (tid == 0)
                    while (ld_acq(&g_wuflag[xq]) < 1u) __nanosleep(128);
            }

            // H1 rows cover t in [32jj, 32jj+32):
            const unsigned tgt =
                (unsigned)SCAN_CTAS * (unsigned)(32 * (jj + 1) + 1);
            if (tid == 0)
                while (ld_acq(barp) < tgt) __nanosleep(256);
            __syncthreads();

            const float* A = H1;
            const uint32_t smem_u32 = (uint32_t)__cvta_generic_to_shared(sm);

            float acc[2][4][4];
#pragma unroll
            for (int a = 0; a < 2; ++a)
#pragma unroll
                for (int b2 = 0; b2 < 4; ++b2)
#pragma unroll
                    for (int e2 = 0; e2 < 4; ++e2) acc[a][b2][e2] = 0.f;

            // cp.async loads: 512 thr, A stage 128x16 = 512 f4 (1 each),
            // B stage 16x128 = 512 f4 (1 each)
            const int arow = tid >> 2;
            const int ac4  = tid & 3;
            const float* aptr0 = A + (size_t)(rowBase + arow) * NL + ac4 * 4;
            const int bkr0 = tid >> 5;
            const int bc0  = tid & 31;
            const float* bptr0 = g_wu + (size_t)bkr0 * NVP + nb + bc0 * 4;

            const uint32_t adst0 = smem_u32 + (arow * 20 + ac4 * 4) * 4;
            const uint32_t bdst0 = smem_u32 + (UST * UAS + bkr0 * 132 + bc0 * 4) * 4;

            const int NKT = NL / UBK;

#pragma unroll
            for (int s = 0; s < UST - 1; ++s) {
                const int kb = s * UBK;
                cp16(adst0 + s * UAS * 4, aptr0 + kb);
                cp16(bdst0 + s * UBS * 4, bptr0 + (size_t)kb * NVP);
                asm volatile("cp.async.commit_group;\n" ::);
            }

            for (int kt = 0; kt < NKT; ++kt) {
                asm volatile("cp.async.wait_group 2;\n" ::);
                __syncthreads();

                if (kt + UST - 1 < NKT) {
                    const int s  = (kt + UST - 1) & (UST - 1);
                    const int kb = (kt + UST - 1) * UBK;
                    cp16(adst0 + s * UAS * 4, aptr0 + kb);
                    cp16(bdst0 + s * UBS * 4, bptr0 + (size_t)kb * NVP);
                }
                asm volatile("cp.async.commit_group;\n" ::);

                const float* Aw = sm + (kt & (UST - 1)) * UAS;
                const float* Bw = sm + UST * UAS + (kt & (UST - 1)) * UBS;
#pragma unroll
                for (int ks = 0; ks < UBK; ks += 8) {
                    unsigned af[2][4], bf[4][2];
#pragma unroll
                    for (int im = 0; im < 2; ++im) {
                        const int m0 = wm * 64 + ws * 32 + im * 16;
                        const float* a0 = Aw + (m0 + g) * 20 + ks + t4;
                        const float* a1 = Aw + (m0 + g + 8) * 20 + ks + t4;
                        af[im][0] = __float_as_uint(a0[0]);
                        af[im][1] = __float_as_uint(a1[0]);
                        af[im][2] = __float_as_uint(a0[4]);
                        af[im][3] = __float_as_uint(a1[4]);
                    }
#pragma unroll
                    for (int in = 0; in < 4; ++in) {
                        const int n0 = wn * 32 + in * 8;
                        bf[in][0] = __float_as_uint(Bw[(ks + t4) * 132 + n0 + g]);
                        bf[in][1] = __float_as_uint(Bw[(ks + t4 + 4) * 132 + n0 + g]);
                    }
#pragma unroll
                    for (int im = 0; im < 2; ++im)
#pragma unroll
                        for (int in = 0; in < 4; ++in)
                            mma_tf32(acc[im][in], af[im], bf[in]);
                }
            }
            // drain remaining groups before smem reuse by next tile
            asm volatile("cp.async.wait_group 0;\n" ::);

#pragma unroll
            for (int im = 0; im < 2; ++im) {
                const int r0 = rowBase + wm * 64 + ws * 32 + im * 16 + g;
#pragma unroll
                for (int in = 0; in < 4; ++in) {
                    const int c0 = nb + wn * 32 + in * 8 + t4 * 2;
#pragma unroll
                    for (int e2 = 0; e2 < 4; ++e2) {
                        const int row = r0 + ((e2 & 2) ? 8 : 0);
                        const int col = c0 + (e2 & 1);
                        if (col < NV) {
                            // T-MAJOR row -> (t, b) -> reference row b*NT+t
                            const int t = row >> 2, b = row & 3;
                            __stcs(&C[((size_t)b * NT + t) * NV + col],
                                   acc[im][in][e2] + bias[col]);
                        }
                    }
                }
            }
        }
    }
}

// ---------------------------------------------------------------------------
// Launch
// ---------------------------------------------------------------------------
extern "C" void kernel_launch(void* const* d_in, const int* in_sizes, int n_in,
                              void* d_out, int out_size) {
    const int*   x     = (const int*)  d_in[0];
    const float* embed = (const float*)d_in[1];
    const float* Wx0   = (const float*)d_in[2];
    const float* Wh0   = (const float*)d_in[3];
    const float* b0    = (const float*)d_in[4];
    const float* Wx1   = (const float*)d_in[5];
    const float* Wh1   = (const float*)d_in[6];
    const float* b1    = (const float*)d_in[7];
    const float* Wu    = (const float*)d_in[8];
    const float* bu    = (const float*)d_in[9];
    float* out = (float*)d_out;

    void *pA = nullptr, *pB = nullptr;
    cudaGetSymbolAddress(&pA, g_bufA);
    cudaGetSymbolAddress(&pB, g_bufB);
    float* bufA = (float*)pA;
    float* bufB = (float*)pB;

    cudaFuncSetAttribute(fused_all,
                         cudaFuncAttributeMaxDynamicSharedMemorySize,
                         FUSED_SMEM);

    init_kernel<<<1, 256>>>();
    fused_all<<<GRID_CTAS, SCAN_THR, FUSED_SMEM>>>(
        x, embed, Wx0, b0, Wh0, Wx1, Wh1, b1, Wu, bu,
        bufA, bufB, out);
}